// round 2
// baseline (speedup 1.0000x reference)
#include <cuda_runtime.h>
#include <math.h>

#define NN 16384
#define NE 65536
#define DD 64
#define GG 512
#define F1 256
#define F2 128
#define EPS 1e-5f

// ---------------- device scratch (no allocs allowed) ----------------
__device__ float g_out[NN * DD];
__device__ float g_h[NN * DD];
__device__ float g_ef[NE * DD];
__device__ float g_A[NN * DD * DD];     // 268 MB: A[n][k*64+o]
__device__ float g_Bt[NN * DD];
__device__ float g_aggr[NN * DD];
__device__ float g_gbuf[NN * DD];
__device__ float g_pooled[GG * DD];
__device__ float g_W2t[2 * DD * DD * DD];   // [layer][i*4096 + k*64 + o]
__device__ float g_wbuf[131072];            // transposed small weights

// offsets (floats) into g_wbuf
#define OFF_LIN0T 0        // 16x64
#define OFF_MLP1T 1024     // 2 x 6x64
#define OFF_WIHT  2048     // 2 x 64x192
#define OFF_WHHT  26624    // 2 x 64x192
#define OFF_RELT  51200    // 64x64
#define OFF_ROOTT 55296    // 64x64
#define OFF_FC1T  59392    // 64x256
#define OFF_FC2T  75776    // 256x128

// ---------------- utility kernels ----------------
__global__ void k_transpose(int dstoff, const float* __restrict__ src, int R, int C) {
    int idx = blockIdx.x * blockDim.x + threadIdx.x;
    if (idx < R * C) {
        int r = idx / C, c = idx % C;
        g_wbuf[dstoff + c * R + r] = src[idx];
    }
}

// W2t[i*4096 + k*64 + o] = mlp2_w[(i*64+o)*64 + k]
__global__ void k_w2t(int layer, const float* __restrict__ src) {
    int idx = blockIdx.x * blockDim.x + threadIdx.x;   // 262144 per layer
    int i = idx >> 12, k = (idx >> 6) & 63, o = idx & 63;
    g_W2t[(layer << 18) + idx] = src[(((i << 6) + o) << 6) + k];
}

__global__ void k_zero_aggr() { g_aggr[blockIdx.x * 256 + threadIdx.x] = 0.f; }
__global__ void k_zero_pooled() { g_pooled[blockIdx.x * 256 + threadIdx.x] = 0.f; }

// ---------------- lin0: out = relu(x @ lin0_w.T + b) ----------------
__global__ void __launch_bounds__(256) k_lin0(const float* __restrict__ x,
                                              const float* __restrict__ b) {
    int t = threadIdx.x;
    int n = blockIdx.x * 4 + (t >> 6);
    int o = t & 63;
    const float* xr = x + n * 16;
    float acc = b[o];
#pragma unroll
    for (int i = 0; i < 16; i++) acc += xr[i] * g_wbuf[OFF_LIN0T + i * 64 + o];
    acc = fmaxf(acc, 0.f);
    g_out[n * 64 + o] = acc;
    g_h[n * 64 + o] = acc;
}

// ---------------- edge MLP1: ef = relu(attr @ w1.T + b1) ----------------
__global__ void __launch_bounds__(256) k_mlp1(const float* __restrict__ attr,
                                              int woff, const float* __restrict__ b1) {
    int t = threadIdx.x;
    int e = blockIdx.x * 4 + (t >> 6);
    int o = t & 63;
    const float* ar = attr + e * 6;
    float acc = b1[o];
#pragma unroll
    for (int k = 0; k < 6; k++) acc += ar[k] * g_wbuf[woff + k * 64 + o];
    g_ef[e * 64 + o] = fmaxf(acc, 0.f);
}

// ---------------- Bterm[n,o] = sum_i out[n,i]*b2[i*64+o] ----------------
__global__ void __launch_bounds__(256) k_bterm(const float* __restrict__ b2) {
    int t = threadIdx.x;
    int n = blockIdx.x * 4 + (t >> 6);
    int o = t & 63;
    const float* xr = g_out + n * 64;
    float acc = 0.f;
#pragma unroll 8
    for (int i = 0; i < 64; i++) acc += xr[i] * b2[i * 64 + o];
    g_Bt[n * 64 + o] = acc;
}

// ---------------- A = out[N,64] @ W2t[64,4096]  (row-major GEMM) ----------------
__global__ void __launch_bounds__(256) k_agemm(int layer) {
    const float* __restrict__ B = g_W2t + (layer << 18);
    __shared__ float Xs[64][65];
    __shared__ __align__(16) float Ws[64][64];
    int j0 = blockIdx.x << 6, m0 = blockIdx.y << 6;
    int t = threadIdx.x;
#pragma unroll
    for (int r = 0; r < 16; r++) {
        int off = (r << 8) + t;
        int a = off >> 6, c = off & 63;
        Xs[a][c] = g_out[((m0 + a) << 6) + c];
        Ws[a][c] = B[(a << 12) + j0 + c];
    }
    __syncthreads();
    int tm = (t >> 4) << 2, tj = (t & 15) << 2;
    float acc[4][4];
#pragma unroll
    for (int a = 0; a < 4; a++)
#pragma unroll
        for (int b = 0; b < 4; b++) acc[a][b] = 0.f;
#pragma unroll
    for (int k = 0; k < 64; k++) {
        float4 bv = *(const float4*)&Ws[k][tj];
        float a0 = Xs[tm][k], a1 = Xs[tm + 1][k], a2 = Xs[tm + 2][k], a3 = Xs[tm + 3][k];
        acc[0][0] += a0 * bv.x; acc[0][1] += a0 * bv.y; acc[0][2] += a0 * bv.z; acc[0][3] += a0 * bv.w;
        acc[1][0] += a1 * bv.x; acc[1][1] += a1 * bv.y; acc[1][2] += a1 * bv.z; acc[1][3] += a1 * bv.w;
        acc[2][0] += a2 * bv.x; acc[2][1] += a2 * bv.y; acc[2][2] += a2 * bv.z; acc[2][3] += a2 * bv.w;
        acc[3][0] += a3 * bv.x; acc[3][1] += a3 * bv.y; acc[3][2] += a3 * bv.z; acc[3][3] += a3 * bv.w;
    }
#pragma unroll
    for (int a = 0; a < 4; a++) {
        float4 v = make_float4(acc[a][0], acc[a][1], acc[a][2], acc[a][3]);
        *(float4*)&g_A[((m0 + tm + a) << 12) + j0 + tj] = v;
    }
}

// ---------------- edge contraction + scatter-add (4 edges / 256-thread block) --
__global__ void __launch_bounds__(256) k_edge(const int* __restrict__ ei) {
    int g = threadIdx.x >> 6;               // edge slot within block
    int e = (blockIdx.x << 2) + g;
    int o = threadIdx.x & 63;
    __shared__ float efs[4][64];
    int src = __ldg(&ei[e]), dst = __ldg(&ei[NE + e]);
    efs[g][o] = g_ef[(e << 6) + o];
    __syncthreads();
    const float* __restrict__ Ar = g_A + (src << 12) + o;
    const float* efp = efs[g];
    float a0 = g_Bt[(src << 6) + o], a1 = 0.f, a2 = 0.f, a3 = 0.f;
#pragma unroll
    for (int k = 0; k < 64; k += 4) {
        a0 += efp[k] * Ar[(k) << 6];
        a1 += efp[k + 1] * Ar[(k + 1) << 6];
        a2 += efp[k + 2] * Ar[(k + 2) << 6];
        a3 += efp[k + 3] * Ar[(k + 3) << 6];
    }
    atomicAdd(&g_aggr[(dst << 6) + o], a0 + a1 + a2 + a3);
}

// ---------------- per-node: root + bias + relu + BN + GRU ----------------
__global__ void __launch_bounds__(256) k_node(const float* __restrict__ rootw,
                                              const float* __restrict__ convb,
                                              const float* __restrict__ bnp,
                                              int wihoff, int whhoff,
                                              const float* __restrict__ bih,
                                              const float* __restrict__ bhh) {
    int t = threadIdx.x;
    int n = blockIdx.x * 4 + (t >> 6);
    int o = t & 63;
    int g = t >> 6;
    __shared__ float ms[4][64], hs[4][64], outs[4][64];
    outs[g][o] = g_out[n * 64 + o];
    hs[g][o] = g_h[n * 64 + o];
    __syncthreads();
    float acc = g_aggr[n * 64 + o] + convb[o];
#pragma unroll 8
    for (int i = 0; i < 64; i++) acc += outs[g][i] * rootw[i * 64 + o];
    acc = fmaxf(acc, 0.f);
    acc = (acc - bnp[128 + o]) * rsqrtf(bnp[192 + o] + EPS) * bnp[o] + bnp[64 + o];
    ms[g][o] = acc;
    __syncthreads();
    float ir = bih[o], iz = bih[64 + o], in_ = bih[128 + o];
    float hr = bhh[o], hz = bhh[64 + o], hn = bhh[128 + o];
    const float* wiT = g_wbuf + wihoff;
    const float* whT = g_wbuf + whhoff;
#pragma unroll 4
    for (int d = 0; d < 64; d++) {
        float md = ms[g][d], hd = hs[g][d];
        const float* wi = wiT + d * 192;
        const float* wh = whT + d * 192;
        ir += md * wi[o];       iz += md * wi[64 + o];  in_ += md * wi[128 + o];
        hr += hd * wh[o];       hz += hd * wh[64 + o];  hn += hd * wh[128 + o];
    }
    float r = 1.f / (1.f + expf(-(ir + hr)));
    float z = 1.f / (1.f + expf(-(iz + hz)));
    float nn_ = tanhf(in_ + r * hn);
    float hnew = (1.f - z) * nn_ + z * hs[g][o];
    g_h[n * 64 + o] = hnew;
    g_out[n * 64 + o] = hnew;
}

// ---------------- GraphConv scatter: aggr[dst] += out[src] ----------------
__global__ void __launch_bounds__(256) k_gcscatter(const int* __restrict__ ei) {
    int t = threadIdx.x;
    int e = blockIdx.x * 4 + (t >> 6);
    int o = t & 63;
    int src = ei[e], dst = ei[NE + e];
    atomicAdd(&g_aggr[dst * 64 + o], g_out[src * 64 + o]);
}

__global__ void __launch_bounds__(256) k_gcnode(const float* __restrict__ relb,
                                                const float* __restrict__ bnl) {
    int t = threadIdx.x;
    int n = blockIdx.x * 4 + (t >> 6);
    int o = t & 63;
    int g = t >> 6;
    __shared__ float as[4][64], os[4][64];
    as[g][o] = g_aggr[n * 64 + o];
    os[g][o] = g_out[n * 64 + o];
    __syncthreads();
    float acc = relb[o];
#pragma unroll 4
    for (int d = 0; d < 64; d++)
        acc += as[g][d] * g_wbuf[OFF_RELT + d * 64 + o] + os[g][d] * g_wbuf[OFF_ROOTT + d * 64 + o];
    acc = fmaxf(acc, 0.f);
    acc = (acc - bnl[128 + o]) * rsqrtf(bnl[192 + o] + EPS) * bnl[o] + bnl[64 + o];
    g_gbuf[n * 64 + o] = acc;
}

__global__ void __launch_bounds__(256) k_pool(const int* __restrict__ batch) {
    int t = threadIdx.x;
    int n = blockIdx.x * 4 + (t >> 6);
    int o = t & 63;
    atomicAdd(&g_pooled[batch[n] * 64 + o], g_gbuf[n * 64 + o]);
}

// ---------------- FC head, one block per graph ----------------
__global__ void __launch_bounds__(256) k_head(const float* __restrict__ fc1b,
                                              const float* __restrict__ bn1,
                                              const float* __restrict__ fc2b,
                                              const float* __restrict__ bn2,
                                              const float* __restrict__ fclw,
                                              const float* __restrict__ fclb,
                                              float* __restrict__ out) {
    int gi = blockIdx.x;
    int t = threadIdx.x;
    __shared__ float ps[64], f1[F1], f2[F2], red[8];
    if (t < 64) ps[t] = g_pooled[gi * 64 + t];
    __syncthreads();
    {
        float acc = fc1b[t];
#pragma unroll 8
        for (int d = 0; d < 64; d++) acc += ps[d] * g_wbuf[OFF_FC1T + d * F1 + t];
        acc = fmaxf(acc, 0.f);
        acc = (acc - bn1[2 * F1 + t]) * rsqrtf(bn1[3 * F1 + t] + EPS) * bn1[t] + bn1[F1 + t];
        f1[t] = acc;
    }
    __syncthreads();
    if (t < F2) {
        float acc = fc2b[t];
#pragma unroll 8
        for (int d = 0; d < F1; d++) acc += f1[d] * g_wbuf[OFF_FC2T + d * F2 + t];
        acc = fmaxf(acc, 0.f);
        acc = (acc - bn2[2 * F2 + t]) * rsqrtf(bn2[3 * F2 + t] + EPS) * bn2[t] + bn2[F2 + t];
        f2[t] = acc;
    }
    __syncthreads();
    float p = (t < F2) ? f2[t] * fclw[t] : 0.f;
#pragma unroll
    for (int s = 16; s > 0; s >>= 1) p += __shfl_down_sync(0xffffffff, p, s);
    if ((t & 31) == 0) red[t >> 5] = p;
    __syncthreads();
    if (t == 0) out[gi] = red[0] + red[1] + red[2] + red[3] + red[4] + red[5] + red[6] + red[7] + fclb[0];
}

// ---------------- launch ----------------
extern "C" void kernel_launch(void* const* d_in, const int* in_sizes, int n_in,
                              void* d_out, int out_size) {
    (void)in_sizes; (void)n_in; (void)out_size;
    const float* x        = (const float*)d_in[0];
    const float* attr     = (const float*)d_in[1];
    const float* lin0_w   = (const float*)d_in[2];
    const float* lin0_b   = (const float*)d_in[3];
    const float* mlp1_w   = (const float*)d_in[4];
    const float* mlp1_b   = (const float*)d_in[5];
    const float* mlp2_w   = (const float*)d_in[6];
    const float* mlp2_b   = (const float*)d_in[7];
    const float* root_w   = (const float*)d_in[8];
    const float* conv_b   = (const float*)d_in[9];
    const float* bn       = (const float*)d_in[10];
    const float* gru_wih  = (const float*)d_in[11];
    const float* gru_whh  = (const float*)d_in[12];
    const float* gru_bih  = (const float*)d_in[13];
    const float* gru_bhh  = (const float*)d_in[14];
    const float* gc_rel_w = (const float*)d_in[15];
    const float* gc_rel_b = (const float*)d_in[16];
    const float* gc_root_w= (const float*)d_in[17];
    const float* bnl      = (const float*)d_in[18];
    const float* fc1_w    = (const float*)d_in[19];
    const float* fc1_b    = (const float*)d_in[20];
    const float* fcbn1    = (const float*)d_in[21];
    const float* fc2_w    = (const float*)d_in[22];
    const float* fc2_b    = (const float*)d_in[23];
    const float* fcbn2    = (const float*)d_in[24];
    const float* fcl_w    = (const float*)d_in[25];
    const float* fcl_b    = (const float*)d_in[26];
    const int*   ei       = (const int*)d_in[27];
    const int*   batch    = (const int*)d_in[28];
    float* out = (float*)d_out;

    // weight transposes (cheap, every call — deterministic)
    k_transpose<<<(64 * 16 + 255) / 256, 256>>>(OFF_LIN0T, lin0_w, 64, 16);
    k_transpose<<<2, 256>>>(OFF_MLP1T, mlp1_w, 64, 6);
    k_transpose<<<2, 256>>>(OFF_MLP1T + 384, mlp1_w + 384, 64, 6);
    k_transpose<<<48, 256>>>(OFF_WIHT, gru_wih, 192, 64);
    k_transpose<<<48, 256>>>(OFF_WIHT + 12288, gru_wih + 12288, 192, 64);
    k_transpose<<<48, 256>>>(OFF_WHHT, gru_whh, 192, 64);
    k_transpose<<<48, 256>>>(OFF_WHHT + 12288, gru_whh + 12288, 192, 64);
    k_transpose<<<16, 256>>>(OFF_RELT, gc_rel_w, 64, 64);
    k_transpose<<<16, 256>>>(OFF_ROOTT, gc_root_w, 64, 64);
    k_transpose<<<64, 256>>>(OFF_FC1T, fc1_w, 256, 64);
    k_transpose<<<128, 256>>>(OFF_FC2T, fc2_w, 128, 256);
    k_w2t<<<1024, 256>>>(0, mlp2_w);
    k_w2t<<<1024, 256>>>(1, mlp2_w + 262144);

    k_lin0<<<NN / 4, 256>>>(x, lin0_b);

    for (int l = 0; l < 2; l++) {
        k_mlp1<<<NE / 4, 256>>>(attr, OFF_MLP1T + l * 384, mlp1_b + l * 64);
        k_bterm<<<NN / 4, 256>>>(mlp2_b + l * 4096);
        k_agemm<<<dim3(64, 256), 256>>>(l);
        k_zero_aggr<<<4096, 256>>>();
        k_edge<<<NE / 4, 256>>>(ei);
        k_node<<<NN / 4, 256>>>(root_w + l * 4096, conv_b + l * 64, bn + l * 256,
                                OFF_WIHT + l * 12288, OFF_WHHT + l * 12288,
                                gru_bih + l * 192, gru_bhh + l * 192);
    }

    k_zero_aggr<<<4096, 256>>>();
    k_gcscatter<<<NE / 4, 256>>>(ei);
    k_gcnode<<<NN / 4, 256>>>(gc_rel_b, bnl);
    k_zero_pooled<<<GG * 64 / 256, 256>>>();
    k_pool<<<NN / 4, 256>>>(batch);
    k_head<<<GG, 256>>>(fc1_b, fcbn1, fc2_b, fcbn2, fcl_w, fcl_b, out);
}

// round 3
// speedup vs baseline: 1.2892x; 1.2892x over previous
#include <cuda_runtime.h>
#include <math.h>
#include <stdint.h>

#define NN 16384
#define NE 65536
#define DD 64
#define GG 512
#define F1 256
#define F2 128
#define EPS 1e-5f

// ---------------- device scratch (no allocs allowed) ----------------
__device__ float g_out[NN * DD];
__device__ float g_h[NN * DD];
__device__ float g_ef[NE * DD];
__device__ float g_A[NN * DD * DD];     // 268 MB: A[n][k*64+o]
__device__ float g_Bt[NN * DD];
__device__ float g_aggr[NN * DD];
__device__ float g_gbuf[NN * DD];
__device__ float g_pooled[GG * DD];
__device__ float g_W2t[2 * DD * DD * DD];   // [layer][i*4096 + (k*64+o)]  (tf32-rounded)
__device__ float g_wbuf[131072];            // transposed small weights
__device__ int   g_cnt[NN];                 // per-src edge counts
__device__ int   g_pos[NN];                 // exclusive offsets (cursor)
__device__ int   g_perm[NE];                // edges sorted by src

// offsets (floats) into g_wbuf
#define OFF_LIN0T 0        // 16x64
#define OFF_MLP1T 1024     // 2 x 6x64
#define OFF_WIHT  2048     // 2 x 64x192
#define OFF_WHHT  26624    // 2 x 64x192
#define OFF_RELT  51200    // 64x64
#define OFF_ROOTT 55296    // 64x64
#define OFF_FC1T  59392    // 64x256
#define OFF_FC2T  75776    // 256x128

// ---------------- tf32 helpers ----------------
__device__ __forceinline__ float cvt_tf32(float x) {
    uint32_t u;
    asm("cvt.rna.tf32.f32 %0, %1;" : "=r"(u) : "f"(x));
    return __uint_as_float(u);
}

__device__ __forceinline__ void mma_tf32(float* d, const uint32_t* a, const uint32_t* b) {
    asm volatile(
        "mma.sync.aligned.m16n8k8.row.col.f32.tf32.tf32.f32 "
        "{%0,%1,%2,%3}, {%4,%5,%6,%7}, {%8,%9}, {%0,%1,%2,%3};\n"
        : "+f"(d[0]), "+f"(d[1]), "+f"(d[2]), "+f"(d[3])
        : "r"(a[0]), "r"(a[1]), "r"(a[2]), "r"(a[3]), "r"(b[0]), "r"(b[1]));
}

// ---------------- utility kernels ----------------
__global__ void k_transpose(int dstoff, const float* __restrict__ src, int R, int C) {
    int idx = blockIdx.x * blockDim.x + threadIdx.x;
    if (idx < R * C) {
        int r = idx / C, c = idx % C;
        g_wbuf[dstoff + c * R + r] = src[idx];
    }
}

// W2t[i*4096 + k*64 + o] = tf32(mlp2_w[(i*64+o)*64 + k])
__global__ void k_w2t(int layer, const float* __restrict__ src) {
    int idx = blockIdx.x * blockDim.x + threadIdx.x;   // 262144 per layer
    int i = idx >> 12, k = (idx >> 6) & 63, o = idx & 63;
    g_W2t[(layer << 18) + idx] = cvt_tf32(src[(((i << 6) + o) << 6) + k]);
}

__global__ void k_zero_aggr() { g_aggr[blockIdx.x * 256 + threadIdx.x] = 0.f; }
__global__ void k_zero_pooled() { g_pooled[blockIdx.x * 256 + threadIdx.x] = 0.f; }
__global__ void k_zero_cnt() { g_cnt[blockIdx.x * 256 + threadIdx.x] = 0; }

// ---------------- counting sort of edges by src ----------------
__global__ void k_hist(const int* __restrict__ ei) {
    int e = blockIdx.x * 256 + threadIdx.x;
    atomicAdd(&g_cnt[ei[e]], 1);
}

__global__ void __launch_bounds__(1024) k_scan() {
    __shared__ int s[1024];
    __shared__ int carry;
    int t = threadIdx.x;
    if (t == 0) carry = 0;
    __syncthreads();
    for (int base = 0; base < NN; base += 1024) {
        int v = g_cnt[base + t];
        s[t] = v;
        __syncthreads();
#pragma unroll
        for (int off = 1; off < 1024; off <<= 1) {
            int x = (t >= off) ? s[t - off] : 0;
            __syncthreads();
            s[t] += x;
            __syncthreads();
        }
        g_pos[base + t] = s[t] - v + carry;   // exclusive prefix
        __syncthreads();
        if (t == 0) carry += s[1023];
        __syncthreads();
    }
}

__global__ void k_scatterperm(const int* __restrict__ ei) {
    int e = blockIdx.x * 256 + threadIdx.x;
    int p = atomicAdd(&g_pos[ei[e]], 1);
    g_perm[p] = e;
}

// ---------------- lin0: out = relu(x @ lin0_w.T + b) ----------------
__global__ void __launch_bounds__(256) k_lin0(const float* __restrict__ x,
                                              const float* __restrict__ b) {
    int t = threadIdx.x;
    int n = blockIdx.x * 4 + (t >> 6);
    int o = t & 63;
    const float* xr = x + n * 16;
    float acc = b[o];
#pragma unroll
    for (int i = 0; i < 16; i++) acc += xr[i] * g_wbuf[OFF_LIN0T + i * 64 + o];
    acc = fmaxf(acc, 0.f);
    g_out[n * 64 + o] = acc;
    g_h[n * 64 + o] = acc;
}

// ---------------- edge MLP1 ----------------
__global__ void __launch_bounds__(256) k_mlp1(const float* __restrict__ attr,
                                              int woff, const float* __restrict__ b1) {
    int t = threadIdx.x;
    int e = blockIdx.x * 4 + (t >> 6);
    int o = t & 63;
    const float* ar = attr + e * 6;
    float acc = b1[o];
#pragma unroll
    for (int k = 0; k < 6; k++) acc += ar[k] * g_wbuf[woff + k * 64 + o];
    g_ef[e * 64 + o] = fmaxf(acc, 0.f);
}

// ---------------- Bterm[n,o] = sum_i out[n,i]*b2[i*64+o] ----------------
__global__ void __launch_bounds__(256) k_bterm(const float* __restrict__ b2) {
    int t = threadIdx.x;
    int n = blockIdx.x * 4 + (t >> 6);
    int o = t & 63;
    const float* xr = g_out + n * 64;
    float acc = 0.f;
#pragma unroll 8
    for (int i = 0; i < 64; i++) acc += xr[i] * b2[i * 64 + o];
    g_Bt[n * 64 + o] = acc;
}

// ---------------- A = out[16384,64] @ W2t[64,4096]  tf32 tensor-core GEMM -------
// block tile 128x128, 4 warps (2x2) each 64x64, K chunks of 16.
__global__ void __launch_bounds__(128) k_agemm_mma(int layer) {
    const float* __restrict__ W = g_W2t + (layer << 18);
    __shared__ float Xs[128][20];     // pad 20: A-load bank = 4*row+col -> all distinct
    __shared__ float Wsm[16][136];    // pad 136: B-load bank = 8*k+n -> all distinct
    int m0 = blockIdx.y << 7;
    int n0 = blockIdx.x << 7;
    int t = threadIdx.x;
    int warp = t >> 5, lane = t & 31;
    int wm = (warp >> 1) << 6;
    int wn = (warp & 1) << 6;
    int group = lane >> 2, tig = lane & 3;

    float acc[4][8][4];
#pragma unroll
    for (int i = 0; i < 4; i++)
#pragma unroll
        for (int j = 0; j < 8; j++)
#pragma unroll
            for (int r = 0; r < 4; r++) acc[i][j][r] = 0.f;

    for (int kc = 0; kc < 64; kc += 16) {
        // X chunk: 128 rows x 16; each thread loads its row (4 float4), cvt tf32
        {
            const float4* src = (const float4*)&g_out[((m0 + t) << 6) + kc];
#pragma unroll
            for (int q = 0; q < 4; q++) {
                float4 v = src[q];
                Xs[t][q * 4 + 0] = cvt_tf32(v.x);
                Xs[t][q * 4 + 1] = cvt_tf32(v.y);
                Xs[t][q * 4 + 2] = cvt_tf32(v.z);
                Xs[t][q * 4 + 3] = cvt_tf32(v.w);
            }
        }
        // W chunk: 16 rows x 128; thread -> row t>>3, cols (t&7)*16 .. +15 (already tf32)
        {
            int kr = t >> 3, c0 = (t & 7) << 4;
            const float4* src = (const float4*)&W[((kc + kr) << 12) + n0 + c0];
#pragma unroll
            for (int q = 0; q < 4; q++) {
                float4 v = src[q];
                Wsm[kr][c0 + q * 4 + 0] = v.x;
                Wsm[kr][c0 + q * 4 + 1] = v.y;
                Wsm[kr][c0 + q * 4 + 2] = v.z;
                Wsm[kr][c0 + q * 4 + 3] = v.w;
            }
        }
        __syncthreads();
#pragma unroll
        for (int ks = 0; ks < 16; ks += 8) {
            uint32_t afr[4][4];
#pragma unroll
            for (int i = 0; i < 4; i++) {
                int r = wm + (i << 4) + group;
                afr[i][0] = __float_as_uint(Xs[r][ks + tig]);
                afr[i][1] = __float_as_uint(Xs[r + 8][ks + tig]);
                afr[i][2] = __float_as_uint(Xs[r][ks + tig + 4]);
                afr[i][3] = __float_as_uint(Xs[r + 8][ks + tig + 4]);
            }
            uint32_t bfr[8][2];
#pragma unroll
            for (int j = 0; j < 8; j++) {
                int n = wn + (j << 3) + group;
                bfr[j][0] = __float_as_uint(Wsm[ks + tig][n]);
                bfr[j][1] = __float_as_uint(Wsm[ks + tig + 4][n]);
            }
#pragma unroll
            for (int i = 0; i < 4; i++)
#pragma unroll
                for (int j = 0; j < 8; j++) mma_tf32(acc[i][j], afr[i], bfr[j]);
        }
        __syncthreads();
    }
    // store accumulators
#pragma unroll
    for (int i = 0; i < 4; i++) {
        int r = m0 + wm + (i << 4) + group;
#pragma unroll
        for (int j = 0; j < 8; j++) {
            int c = n0 + wn + (j << 3) + (tig << 1);
            *(float2*)&g_A[(r << 12) + c]       = make_float2(acc[i][j][0], acc[i][j][1]);
            *(float2*)&g_A[((r + 8) << 12) + c] = make_float2(acc[i][j][2], acc[i][j][3]);
        }
    }
}

// ---------------- edge contraction + scatter-add (src-sorted order) ----------
__global__ void __launch_bounds__(256) k_edge(const int* __restrict__ ei) {
    int g = threadIdx.x >> 6;
    int e = g_perm[(blockIdx.x << 2) + g];
    int o = threadIdx.x & 63;
    __shared__ float efs[4][64];
    int src = __ldg(&ei[e]), dst = __ldg(&ei[NE + e]);
    efs[g][o] = g_ef[(e << 6) + o];
    __syncthreads();
    const float* __restrict__ Ar = g_A + (src << 12) + o;
    const float* efp = efs[g];
    float a0 = g_Bt[(src << 6) + o], a1 = 0.f, a2 = 0.f, a3 = 0.f;
#pragma unroll
    for (int k = 0; k < 64; k += 4) {
        a0 += efp[k] * Ar[(k) << 6];
        a1 += efp[k + 1] * Ar[(k + 1) << 6];
        a2 += efp[k + 2] * Ar[(k + 2) << 6];
        a3 += efp[k + 3] * Ar[(k + 3) << 6];
    }
    atomicAdd(&g_aggr[(dst << 6) + o], a0 + a1 + a2 + a3);
}

// ---------------- per-node: root + bias + relu + BN + GRU ----------------
__global__ void __launch_bounds__(256) k_node(const float* __restrict__ rootw,
                                              const float* __restrict__ convb,
                                              const float* __restrict__ bnp,
                                              int wihoff, int whhoff,
                                              const float* __restrict__ bih,
                                              const float* __restrict__ bhh) {
    int t = threadIdx.x;
    int n = blockIdx.x * 4 + (t >> 6);
    int o = t & 63;
    int g = t >> 6;
    __shared__ float ms[4][64], hs[4][64], outs[4][64];
    outs[g][o] = g_out[n * 64 + o];
    hs[g][o] = g_h[n * 64 + o];
    __syncthreads();
    float acc = g_aggr[n * 64 + o] + convb[o];
#pragma unroll 8
    for (int i = 0; i < 64; i++) acc += outs[g][i] * rootw[i * 64 + o];
    acc = fmaxf(acc, 0.f);
    acc = (acc - bnp[128 + o]) * rsqrtf(bnp[192 + o] + EPS) * bnp[o] + bnp[64 + o];
    ms[g][o] = acc;
    __syncthreads();
    float ir = bih[o], iz = bih[64 + o], in_ = bih[128 + o];
    float hr = bhh[o], hz = bhh[64 + o], hn = bhh[128 + o];
    const float* wiT = g_wbuf + wihoff;
    const float* whT = g_wbuf + whhoff;
#pragma unroll 4
    for (int d = 0; d < 64; d++) {
        float md = ms[g][d], hd = hs[g][d];
        const float* wi = wiT + d * 192;
        const float* wh = whT + d * 192;
        ir += md * wi[o];       iz += md * wi[64 + o];  in_ += md * wi[128 + o];
        hr += hd * wh[o];       hz += hd * wh[64 + o];  hn += hd * wh[128 + o];
    }
    float r = 1.f / (1.f + expf(-(ir + hr)));
    float z = 1.f / (1.f + expf(-(iz + hz)));
    float nn_ = tanhf(in_ + r * hn);
    float hnew = (1.f - z) * nn_ + z * hs[g][o];
    g_h[n * 64 + o] = hnew;
    g_out[n * 64 + o] = hnew;
}

// ---------------- GraphConv scatter (src-sorted order) ----------------
__global__ void __launch_bounds__(256) k_gcscatter(const int* __restrict__ ei) {
    int t = threadIdx.x;
    int e = g_perm[blockIdx.x * 4 + (t >> 6)];
    int o = t & 63;
    int src = ei[e], dst = ei[NE + e];
    atomicAdd(&g_aggr[dst * 64 + o], g_out[src * 64 + o]);
}

__global__ void __launch_bounds__(256) k_gcnode(const float* __restrict__ relb,
                                                const float* __restrict__ bnl) {
    int t = threadIdx.x;
    int n = blockIdx.x * 4 + (t >> 6);
    int o = t & 63;
    int g = t >> 6;
    __shared__ float as[4][64], os[4][64];
    as[g][o] = g_aggr[n * 64 + o];
    os[g][o] = g_out[n * 64 + o];
    __syncthreads();
    float acc = relb[o];
#pragma unroll 4
    for (int d = 0; d < 64; d++)
        acc += as[g][d] * g_wbuf[OFF_RELT + d * 64 + o] + os[g][d] * g_wbuf[OFF_ROOTT + d * 64 + o];
    acc = fmaxf(acc, 0.f);
    acc = (acc - bnl[128 + o]) * rsqrtf(bnl[192 + o] + EPS) * bnl[o] + bnl[64 + o];
    g_gbuf[n * 64 + o] = acc;
}

__global__ void __launch_bounds__(256) k_pool(const int* __restrict__ batch) {
    int t = threadIdx.x;
    int n = blockIdx.x * 4 + (t >> 6);
    int o = t & 63;
    atomicAdd(&g_pooled[batch[n] * 64 + o], g_gbuf[n * 64 + o]);
}

// ---------------- FC head, one block per graph ----------------
__global__ void __launch_bounds__(256) k_head(const float* __restrict__ fc1b,
                                              const float* __restrict__ bn1,
                                              const float* __restrict__ fc2b,
                                              const float* __restrict__ bn2,
                                              const float* __restrict__ fclw,
                                              const float* __restrict__ fclb,
                                              float* __restrict__ out) {
    int gi = blockIdx.x;
    int t = threadIdx.x;
    __shared__ float ps[64], f1[F1], f2[F2], red[8];
    if (t < 64) ps[t] = g_pooled[gi * 64 + t];
    __syncthreads();
    {
        float acc = fc1b[t];
#pragma unroll 8
        for (int d = 0; d < 64; d++) acc += ps[d] * g_wbuf[OFF_FC1T + d * F1 + t];
        acc = fmaxf(acc, 0.f);
        acc = (acc - bn1[2 * F1 + t]) * rsqrtf(bn1[3 * F1 + t] + EPS) * bn1[t] + bn1[F1 + t];
        f1[t] = acc;
    }
    __syncthreads();
    if (t < F2) {
        float acc = fc2b[t];
#pragma unroll 8
        for (int d = 0; d < F1; d++) acc += f1[d] * g_wbuf[OFF_FC2T + d * F2 + t];
        acc = fmaxf(acc, 0.f);
        acc = (acc - bn2[2 * F2 + t]) * rsqrtf(bn2[3 * F2 + t] + EPS) * bn2[t] + bn2[F2 + t];
        f2[t] = acc;
    }
    __syncthreads();
    float p = (t < F2) ? f2[t] * fclw[t] : 0.f;
#pragma unroll
    for (int s = 16; s > 0; s >>= 1) p += __shfl_down_sync(0xffffffff, p, s);
    if ((t & 31) == 0) red[t >> 5] = p;
    __syncthreads();
    if (t == 0) out[gi] = red[0] + red[1] + red[2] + red[3] + red[4] + red[5] + red[6] + red[7] + fclb[0];
}

// ---------------- launch ----------------
extern "C" void kernel_launch(void* const* d_in, const int* in_sizes, int n_in,
                              void* d_out, int out_size) {
    (void)in_sizes; (void)n_in; (void)out_size;
    const float* x        = (const float*)d_in[0];
    const float* attr     = (const float*)d_in[1];
    const float* lin0_w   = (const float*)d_in[2];
    const float* lin0_b   = (const float*)d_in[3];
    const float* mlp1_w   = (const float*)d_in[4];
    const float* mlp1_b   = (const float*)d_in[5];
    const float* mlp2_w   = (const float*)d_in[6];
    const float* mlp2_b   = (const float*)d_in[7];
    const float* root_w   = (const float*)d_in[8];
    const float* conv_b   = (const float*)d_in[9];
    const float* bn       = (const float*)d_in[10];
    const float* gru_wih  = (const float*)d_in[11];
    const float* gru_whh  = (const float*)d_in[12];
    const float* gru_bih  = (const float*)d_in[13];
    const float* gru_bhh  = (const float*)d_in[14];
    const float* gc_rel_w = (const float*)d_in[15];
    const float* gc_rel_b = (const float*)d_in[16];
    const float* gc_root_w= (const float*)d_in[17];
    const float* bnl      = (const float*)d_in[18];
    const float* fc1_w    = (const float*)d_in[19];
    const float* fc1_b    = (const float*)d_in[20];
    const float* fcbn1    = (const float*)d_in[21];
    const float* fc2_w    = (const float*)d_in[22];
    const float* fc2_b    = (const float*)d_in[23];
    const float* fcbn2    = (const float*)d_in[24];
    const float* fcl_w    = (const float*)d_in[25];
    const float* fcl_b    = (const float*)d_in[26];
    const int*   ei       = (const int*)d_in[27];
    const int*   batch    = (const int*)d_in[28];
    float* out = (float*)d_out;

    // weight transposes
    k_transpose<<<(64 * 16 + 255) / 256, 256>>>(OFF_LIN0T, lin0_w, 64, 16);
    k_transpose<<<2, 256>>>(OFF_MLP1T, mlp1_w, 64, 6);
    k_transpose<<<2, 256>>>(OFF_MLP1T + 384, mlp1_w + 384, 64, 6);
    k_transpose<<<48, 256>>>(OFF_WIHT, gru_wih, 192, 64);
    k_transpose<<<48, 256>>>(OFF_WIHT + 12288, gru_wih + 12288, 192, 64);
    k_transpose<<<48, 256>>>(OFF_WHHT, gru_whh, 192, 64);
    k_transpose<<<48, 256>>>(OFF_WHHT + 12288, gru_whh + 12288, 192, 64);
    k_transpose<<<16, 256>>>(OFF_RELT, gc_rel_w, 64, 64);
    k_transpose<<<16, 256>>>(OFF_ROOTT, gc_root_w, 64, 64);
    k_transpose<<<64, 256>>>(OFF_FC1T, fc1_w, 256, 64);
    k_transpose<<<128, 256>>>(OFF_FC2T, fc2_w, 128, 256);
    k_w2t<<<1024, 256>>>(0, mlp2_w);
    k_w2t<<<1024, 256>>>(1, mlp2_w + 262144);

    // counting sort of edges by src (perm reused across layers + GraphConv)
    k_zero_cnt<<<NN / 256, 256>>>();
    k_hist<<<NE / 256, 256>>>(ei);
    k_scan<<<1, 1024>>>();
    k_scatterperm<<<NE / 256, 256>>>(ei);

    k_lin0<<<NN / 4, 256>>>(x, lin0_b);

    for (int l = 0; l < 2; l++) {
        k_mlp1<<<NE / 4, 256>>>(attr, OFF_MLP1T + l * 384, mlp1_b + l * 64);
        k_bterm<<<NN / 4, 256>>>(mlp2_b + l * 4096);
        k_agemm_mma<<<dim3(32, 128), 128>>>(l);
        k_zero_aggr<<<4096, 256>>>();
        k_edge<<<NE / 4, 256>>>(ei);
        k_node<<<NN / 4, 256>>>(root_w + l * 4096, conv_b + l * 64, bn + l * 256,
                                OFF_WIHT + l * 12288, OFF_WHHT + l * 12288,
                                gru_bih + l * 192, gru_bhh + l * 192);
    }

    k_zero_aggr<<<4096, 256>>>();
    k_gcscatter<<<NE / 4, 256>>>(ei);
    k_gcnode<<<NN / 4, 256>>>(gc_rel_b, bnl);
    k_zero_pooled<<<GG * 64 / 256, 256>>>();
    k_pool<<<NN / 4, 256>>>(batch);
    k_head<<<GG, 256>>>(fc1_b, fcbn1, fc2_b, fcbn2, fcl_w, fcl_b, out);
}